// round 16
// baseline (speedup 1.0000x reference)
#include <cuda_runtime.h>
#include <cuda_bf16.h>
#include <cstdint>

#define NPOS 9
#define NROWS 16384              // T*B
#define D 128
#define TILE_M 64
#define GRID_CTAS 264            // max items = 256 + 8; zero-sync -> waves don't matter
#define NTHREADS 256

// smem map (bytes): A fragments for 64 rows + B uint4 slots + aux
#define OFF_AHI 0                // 16KB
#define OFF_ALO 16384            // 16KB
#define OFF_B   32768            // 128 slots x 512B = 64KB, uint4 {BH0,BH1,BL0,BL1}
#define OFF_AUX 98304
#define SMEM_BYTES (98304 + 1024)

__device__ __forceinline__ void split2(float x, float y, uint32_t& hi, uint32_t& lo) {
    __nv_bfloat162 h = __floats2bfloat162_rn(x, y);
    float hx = __bfloat162float(h.x), hy = __bfloat162float(h.y);
    __nv_bfloat162 l = __floats2bfloat162_rn(x - hx, y - hy);
    hi = *(uint32_t*)&h;
    lo = *(uint32_t*)&l;
}

#define MMA16816(c0, c1, c2, c3, a0, a1, a2, a3, b0, b1)                      \
    asm volatile(                                                             \
        "mma.sync.aligned.m16n8k16.row.col.f32.bf16.bf16.f32 "                \
        "{%0,%1,%2,%3}, {%4,%5,%6,%7}, {%8,%9}, {%0,%1,%2,%3};"               \
        : "+f"(c0), "+f"(c1), "+f"(c2), "+f"(c3)                              \
        : "r"(a0), "r"(a1), "r"(a2), "r"(a3), "r"(b0), "r"(b1))

__global__ void __launch_bounds__(NTHREADS, 2)
fused_transfer(const void* __restrict__ pos_raw,
               const float* __restrict__ x,
               const float* __restrict__ table,
               float* __restrict__ out)
{
    extern __shared__ char base[];
    int* perm     = (int*)(base + OFF_AUX);                       // [64]
    int* swarp    = perm + 64;                                    // [16]
    unsigned long long* sred = (unsigned long long*)(swarp + 16); // [24]
    unsigned long long* stot = sred + 24;                         // [3]

    const int tid  = threadIdx.x;
    const int cid  = blockIdx.x;
    const int wid  = tid >> 5;
    const int lane = tid & 31;
    const int g    = lane >> 2;
    const int tig  = lane & 3;

    // ---- dtype probe: first 256 int32 words, valid under both views; int64
    // => odd words are zero high-words (values 0..15). ----
    const int* pos32 = (const int*)pos_raw;
    int pw = pos32[tid];
    int is32 = __syncthreads_or((tid & 1) && (pw != 0));

    // ---- redundant full-histogram, vectorized: thread owns rows
    // k*1024 + 4*tid + i (k=0..15, i=0..3); j = k*4+i. ----
    unsigned long long cnt0 = 0, cnt1 = 0;      // 9 x 7-bit packed counters
    uint32_t rp[8] = {0, 0, 0, 0, 0, 0, 0, 0};  // 64 r-values, 4 bits each
    if (is32) {
        const int4* pv = (const int4*)pos_raw;
        #pragma unroll
        for (int k = 0; k < 16; k++) {
            int4 w = pv[k * 256 + tid];
            int r0 = (w.x < 8) ? w.x : 8;
            int r1 = (w.y < 8) ? w.y : 8;
            int r2 = (w.z < 8) ? w.z : 8;
            int r3 = (w.w < 8) ? w.w : 8;
            cnt0 += (1ull << (r0 * 7)) + (1ull << (r2 * 7));
            cnt1 += (1ull << (r1 * 7)) + (1ull << (r3 * 7));
            uint32_t packed = (uint32_t)r0 | ((uint32_t)r1 << 4) |
                              ((uint32_t)r2 << 8) | ((uint32_t)r3 << 12);
            rp[k >> 1] |= packed << ((k & 1) * 16);
        }
    } else {
        const longlong2* pv2 = (const longlong2*)pos_raw;
        #pragma unroll
        for (int k = 0; k < 16; k++) {
            longlong2 a = pv2[k * 512 + 2 * tid];
            longlong2 b = pv2[k * 512 + 2 * tid + 1];
            int r0 = (a.x < 8) ? (int)a.x : 8;
            int r1 = (a.y < 8) ? (int)a.y : 8;
            int r2 = (b.x < 8) ? (int)b.x : 8;
            int r3 = (b.y < 8) ? (int)b.y : 8;
            cnt0 += (1ull << (r0 * 7)) + (1ull << (r2 * 7));
            cnt1 += (1ull << (r1 * 7)) + (1ull << (r3 * 7));
            uint32_t packed = (uint32_t)r0 | ((uint32_t)r1 << 4) |
                              ((uint32_t)r2 << 8) | ((uint32_t)r3 << 12);
            rp[k >> 1] |= packed << ((k & 1) * 16);
        }
    }
    unsigned long long cnt = cnt0 + cnt1;

    // ---- reduce counts: expand to 3 u64 (21-bit fields), shuffle + smem ----
    unsigned long long e0 = 0, e1 = 0, e2 = 0;
    #pragma unroll
    for (int q = 0; q < 3; q++) {
        e0 |= ((cnt >> ((0 + q) * 7)) & 127ull) << (q * 21);
        e1 |= ((cnt >> ((3 + q) * 7)) & 127ull) << (q * 21);
        e2 |= ((cnt >> ((6 + q) * 7)) & 127ull) << (q * 21);
    }
    #pragma unroll
    for (int d2 = 16; d2 >= 1; d2 >>= 1) {
        e0 += __shfl_xor_sync(0xFFFFFFFFu, e0, d2);
        e1 += __shfl_xor_sync(0xFFFFFFFFu, e1, d2);
        e2 += __shfl_xor_sync(0xFFFFFFFFu, e2, d2);
    }
    if (lane == 0) { sred[wid * 3] = e0; sred[wid * 3 + 1] = e1; sred[wid * 3 + 2] = e2; }
    __syncthreads();
    if (tid == 0) {
        unsigned long long t0 = 0, t1 = 0, t2 = 0;
        #pragma unroll
        for (int w = 0; w < 8; w++) {
            t0 += sred[w * 3]; t1 += sred[w * 3 + 1]; t2 += sred[w * 3 + 2];
        }
        stot[0] = t0; stot[1] = t1; stot[2] = t2;
    }
    __syncthreads();

    int C[NPOS];
    unsigned long long st0 = stot[0], st1 = stot[1], st2 = stot[2];
    #pragma unroll
    for (int q = 0; q < 3; q++) {
        C[q]     = (int)((st0 >> (q * 21)) & 0x1FFFFF);
        C[3 + q] = (int)((st1 >> (q * 21)) & 0x1FFFFF);
        C[6 + q] = (int)((st2 >> (q * 21)) & 0x1FFFFF);
    }

    // ---- decode own item (uniform per CTA): 64-row chunks ----
    int myp = -1, chunk = 0, total = 0;
    #pragma unroll
    for (int i = 0; i < NPOS; i++) {
        int it = (C[i] + TILE_M - 1) >> 6;
        if (cid >= total && cid < total + it) { myp = i; chunk = cid - total; }
        total += it;
    }
    if (myp < 0) return;
    int nrows = C[myp] - chunk * TILE_M;
    if (nrows > TILE_M) nrows = TILE_M;

    // ---- B convert inline (no big hoist; unroll 4 keeps pressure low) ----
    {
        const float* Mg = table + myp * D * D;
        #pragma unroll 4
        for (int it = 0; it < 16; it++) {
            int qn = wid + it * 8;          // 0..127
            int q = qn >> 4, nb = qn & 15;
            int e = nb * 8 + g;
            int k0 = 16 * q + 2 * tig;
            float v0 = Mg[(k0    ) * D + e];
            float v1 = Mg[(k0 + 1) * D + e];
            float v2 = Mg[(k0 + 8) * D + e];
            float v3 = Mg[(k0 + 9) * D + e];
            uint32_t h0, l0, h1, l1;
            split2(v0, v1, h0, l0);
            split2(v2, v3, h1, l1);
            *(uint4*)(base + OFF_B + qn * 512 + lane * 16) = make_uint4(h0, h1, l0, l1);
        }
    }

    // ---- exclusive scan over per-thread counts of group myp ----
    unsigned lc = (unsigned)((cnt >> (myp * 7)) & 127);
    unsigned v = lc;
    #pragma unroll
    for (int d2 = 1; d2 < 32; d2 <<= 1) {
        unsigned n = __shfl_up_sync(0xFFFFFFFFu, v, d2);
        if (lane >= d2) v += n;
    }
    if (lane == 31) swarp[wid] = (int)v;
    __syncthreads();
    if (tid == 0) {
        int acc = 0;
        #pragma unroll
        for (int w = 0; w < 8; w++) { int t = swarp[w]; swarp[8 + w] = acc; acc += t; }
    }
    __syncthreads();
    int rank0 = swarp[8 + wid] + (int)(v - lc);

    // ---- perm extraction (warp-skip + unrolled): ranks in
    // [chunk*64, chunk*64+nrows). row(tid,j) = (j>>2)*1024 + 4*tid + (j&3). ----
    {
        int wstart = chunk * TILE_M;
        int wend   = wstart + nrows;
        int warp_lo = __shfl_sync(0xFFFFFFFFu, rank0, 0);
        int warp_hi = __shfl_sync(0xFFFFFFFFu, rank0 + (int)lc, 31);
        if (warp_hi > wstart && warp_lo < wend) {
            int rank = rank0;
            #pragma unroll
            for (int j = 0; j < 64; j++) {
                int r = (rp[j >> 3] >> ((j & 7) * 4)) & 15;
                if (r == myp) {
                    if (rank >= wstart && rank < wend)
                        perm[rank - wstart] = (j >> 2) * 1024 + 4 * tid + (j & 3);
                    rank++;
                }
            }
        }
    }
    __syncthreads();      // perm ready

    // ---- A loads hoisted (perm-dependent): 4 threads/row, 2 q each ----
    int rA = tid >> 2;                    // 0..63
    int kq = tid & 3;
    int growA = (rA < nrows) ? perm[rA] : -1;
    float4 Areg[8];
    #pragma unroll
    for (int qq = 0; qq < 2; qq++) {
        if (growA >= 0) {
            const float4* src = (const float4*)(x + growA * D + (kq * 2 + qq) * 16);
            Areg[qq * 4 + 0] = src[0];
            Areg[qq * 4 + 1] = src[1];
            Areg[qq * 4 + 2] = src[2];
            Areg[qq * 4 + 3] = src[3];
        } else {
            Areg[qq * 4 + 0] = Areg[qq * 4 + 1] = Areg[qq * 4 + 2] = Areg[qq * 4 + 3] =
                make_float4(0.f, 0.f, 0.f, 0.f);
        }
    }

    // ---- A split + STS ----
    {
        int aw = rA >> 4, rr = rA & 15, gg = rr & 7, up = rr >> 3;
        #pragma unroll
        for (int qq = 0; qq < 2; qq++) {
            int q = kq * 2 + qq;
            const float* kv = (const float*)&Areg[qq * 4];   // 16 consecutive floats
            #pragma unroll
            for (int t = 0; t < 4; t++) {
                uint32_t hL, lL, hH, lH;
                split2(kv[2 * t], kv[2 * t + 1], hL, lL);
                split2(kv[2 * t + 8], kv[2 * t + 9], hH, lH);
                uint32_t off = (aw * 8 + q) * 512 + (gg * 4 + t) * 16 + up * 4;
                *(uint32_t*)(base + OFF_AHI + off)     = hL;
                *(uint32_t*)(base + OFF_AHI + off + 8) = hH;
                *(uint32_t*)(base + OFF_ALO + off)     = lL;
                *(uint32_t*)(base + OFF_ALO + off + 8) = lH;
            }
        }
    }
    __syncthreads();      // A + B fragments ready

    // ---- mainloop: warp = 16-row block (wid&3) x 64-col half (wid>>2) ----
    const int blk = wid & 3;
    const int ch  = wid >> 2;
    float acc[8][4];
    #pragma unroll
    for (int nb = 0; nb < 8; nb++)
        #pragma unroll
        for (int r = 0; r < 4; r++) acc[nb][r] = 0.f;

    #pragma unroll
    for (int q = 0; q < 8; q++) {
        uint32_t abase = (blk * 8 + q) * 512 + lane * 16;
        uint4 AH = *(const uint4*)(base + OFF_AHI + abase);
        uint4 AL = *(const uint4*)(base + OFF_ALO + abase);
        #pragma unroll
        for (int nb = 0; nb < 8; nb++) {
            uint4 bv = *(const uint4*)(base + OFF_B + (q * 16 + ch * 8 + nb) * 512 + lane * 16);
            MMA16816(acc[nb][0], acc[nb][1], acc[nb][2], acc[nb][3],
                     AH.x, AH.y, AH.z, AH.w, bv.x, bv.y);
            MMA16816(acc[nb][0], acc[nb][1], acc[nb][2], acc[nb][3],
                     AH.x, AH.y, AH.z, AH.w, bv.z, bv.w);
            MMA16816(acc[nb][0], acc[nb][1], acc[nb][2], acc[nb][3],
                     AL.x, AL.y, AL.z, AL.w, bv.x, bv.y);
        }
    }

    // ---- epilogue ----
    {
        int r0 = blk * 16 + g;
        int r1 = r0 + 8;
        int grow0 = (r0 < nrows) ? perm[r0] : -1;
        int grow1 = (r1 < nrows) ? perm[r1] : -1;
        #pragma unroll
        for (int nb = 0; nb < 8; nb++) {
            int col = (ch * 8 + nb) * 8 + 2 * tig;
            if (grow0 >= 0)
                *(float2*)(out + grow0 * D + col) = make_float2(acc[nb][0], acc[nb][1]);
            if (grow1 >= 0)
                *(float2*)(out + grow1 * D + col) = make_float2(acc[nb][2], acc[nb][3]);
        }
    }
}

// ---------------------------------------------------------------------------
extern "C" void kernel_launch(void* const* d_in, const int* in_sizes, int n_in,
                              void* d_out, int out_size) {
    const void*  positions = d_in[0];                 // int32/int64 [T,B] auto-detected
    const float* outputs   = (const float*)d_in[1];   // f32 [T,B,128]
    const float* table     = (const float*)d_in[2];   // f32 [9,128,128]
    float*       out       = (float*)d_out;           // f32 [T,B,128]
    (void)in_sizes; (void)n_in; (void)out_size;

    static cudaError_t attr_once = cudaFuncSetAttribute(
        fused_transfer, cudaFuncAttributeMaxDynamicSharedMemorySize, SMEM_BYTES);
    (void)attr_once;

    fused_transfer<<<GRID_CTAS, NTHREADS, SMEM_BYTES>>>(positions, outputs, table, out);
}

// round 17
// speedup vs baseline: 1.2166x; 1.2166x over previous
#include <cuda_runtime.h>
#include <cuda_bf16.h>
#include <cstdint>

#define NPOS 9
#define NROWS 16384              // T*B
#define D 128
#define TILE_M 128
#define GRID_CTAS 136            // max items = 128 + 8; <= 148 SMs, one wave
#define NTHREADS 256

// smem map (bytes)
#define OFF_AHI 0
#define OFF_ALO 32768
#define OFF_B   65536            // 128 slots x 512B: uint4 {BH0,BH1,BL0,BL1} per (qn,lane)
#define OFF_AUX 131072           // perm[128], swarp[16], sred[24 u64], stot[3 u64]
#define SMEM_BYTES (131072 + 1024)

__device__ __forceinline__ void split2(float x, float y, uint32_t& hi, uint32_t& lo) {
    __nv_bfloat162 h = __floats2bfloat162_rn(x, y);
    float hx = __bfloat162float(h.x), hy = __bfloat162float(h.y);
    __nv_bfloat162 l = __floats2bfloat162_rn(x - hx, y - hy);
    hi = *(uint32_t*)&h;
    lo = *(uint32_t*)&l;
}

#define MMA16816(c0, c1, c2, c3, a0, a1, a2, a3, b0, b1)                      \
    asm volatile(                                                             \
        "mma.sync.aligned.m16n8k16.row.col.f32.bf16.bf16.f32 "                \
        "{%0,%1,%2,%3}, {%4,%5,%6,%7}, {%8,%9}, {%0,%1,%2,%3};"               \
        : "+f"(c0), "+f"(c1), "+f"(c2), "+f"(c3)                              \
        : "r"(a0), "r"(a1), "r"(a2), "r"(a3), "r"(b0), "r"(b1))

__global__ void __launch_bounds__(NTHREADS, 1)
fused_transfer(const void* __restrict__ pos_raw,
               const float* __restrict__ x,
               const float* __restrict__ table,
               float* __restrict__ out)
{
    extern __shared__ char base[];
    int* perm     = (int*)(base + OFF_AUX);                       // [128]
    int* swarp    = perm + 128;                                   // [16]
    unsigned long long* sred = (unsigned long long*)(swarp + 16); // [24]
    unsigned long long* stot = sred + 24;                         // [3]

    const int tid  = threadIdx.x;
    const int cid  = blockIdx.x;
    const int wid  = tid >> 5;
    const int lane = tid & 31;
    const int g    = lane >> 2;
    const int tig  = lane & 3;

    // ---- dtype probe: first 256 int32 words, valid under both views; int64
    // => odd words are zero high-words (values 0..15). ----
    const int* pos32 = (const int*)pos_raw;
    int pw = pos32[tid];
    int is32 = __syncthreads_or((tid & 1) && (pw != 0));

    // ---- redundant full-histogram, vectorized: thread owns rows
    // k*1024 + 4*tid + i (k=0..15, i=0..3); j = k*4+i. ----
    unsigned long long cnt0 = 0, cnt1 = 0;      // 9 x 7-bit packed counters
    uint32_t rp[8] = {0, 0, 0, 0, 0, 0, 0, 0};  // 64 r-values, 4 bits each
    if (is32) {
        const int4* pv = (const int4*)pos_raw;
        #pragma unroll
        for (int k = 0; k < 16; k++) {
            int4 w = pv[k * 256 + tid];
            int r0 = (w.x < 8) ? w.x : 8;
            int r1 = (w.y < 8) ? w.y : 8;
            int r2 = (w.z < 8) ? w.z : 8;
            int r3 = (w.w < 8) ? w.w : 8;
            cnt0 += (1ull << (r0 * 7)) + (1ull << (r2 * 7));
            cnt1 += (1ull << (r1 * 7)) + (1ull << (r3 * 7));
            uint32_t packed = (uint32_t)r0 | ((uint32_t)r1 << 4) |
                              ((uint32_t)r2 << 8) | ((uint32_t)r3 << 12);
            rp[k >> 1] |= packed << ((k & 1) * 16);
        }
    } else {
        const longlong2* pv2 = (const longlong2*)pos_raw;
        #pragma unroll
        for (int k = 0; k < 16; k++) {
            longlong2 a = pv2[k * 512 + 2 * tid];
            longlong2 b = pv2[k * 512 + 2 * tid + 1];
            int r0 = (a.x < 8) ? (int)a.x : 8;
            int r1 = (a.y < 8) ? (int)a.y : 8;
            int r2 = (b.x < 8) ? (int)b.x : 8;
            int r3 = (b.y < 8) ? (int)b.y : 8;
            cnt0 += (1ull << (r0 * 7)) + (1ull << (r2 * 7));
            cnt1 += (1ull << (r1 * 7)) + (1ull << (r3 * 7));
            uint32_t packed = (uint32_t)r0 | ((uint32_t)r1 << 4) |
                              ((uint32_t)r2 << 8) | ((uint32_t)r3 << 12);
            rp[k >> 1] |= packed << ((k & 1) * 16);
        }
    }
    unsigned long long cnt = cnt0 + cnt1;

    // ---- reduce counts: expand to 3 u64 (21-bit fields), shuffle + smem ----
    unsigned long long e0 = 0, e1 = 0, e2 = 0;
    #pragma unroll
    for (int q = 0; q < 3; q++) {
        e0 |= ((cnt >> ((0 + q) * 7)) & 127ull) << (q * 21);
        e1 |= ((cnt >> ((3 + q) * 7)) & 127ull) << (q * 21);
        e2 |= ((cnt >> ((6 + q) * 7)) & 127ull) << (q * 21);
    }
    #pragma unroll
    for (int d2 = 16; d2 >= 1; d2 >>= 1) {
        e0 += __shfl_xor_sync(0xFFFFFFFFu, e0, d2);
        e1 += __shfl_xor_sync(0xFFFFFFFFu, e1, d2);
        e2 += __shfl_xor_sync(0xFFFFFFFFu, e2, d2);
    }
    if (lane == 0) { sred[wid * 3] = e0; sred[wid * 3 + 1] = e1; sred[wid * 3 + 2] = e2; }
    __syncthreads();
    if (tid == 0) {
        unsigned long long t0 = 0, t1 = 0, t2 = 0;
        #pragma unroll
        for (int w = 0; w < 8; w++) {
            t0 += sred[w * 3]; t1 += sred[w * 3 + 1]; t2 += sred[w * 3 + 2];
        }
        stot[0] = t0; stot[1] = t1; stot[2] = t2;
    }
    __syncthreads();

    int C[NPOS];
    unsigned long long st0 = stot[0], st1 = stot[1], st2 = stot[2];
    #pragma unroll
    for (int q = 0; q < 3; q++) {
        C[q]     = (int)((st0 >> (q * 21)) & 0x1FFFFF);
        C[3 + q] = (int)((st1 >> (q * 21)) & 0x1FFFFF);
        C[6 + q] = (int)((st2 >> (q * 21)) & 0x1FFFFF);
    }

    // ---- decode own item (uniform per CTA) ----
    int myp = -1, chunk = 0, total = 0;
    #pragma unroll
    for (int i = 0; i < NPOS; i++) {
        int it = (C[i] + TILE_M - 1) >> 7;
        if (cid >= total && cid < total + it) { myp = i; chunk = cid - total; }
        total += it;
    }
    if (myp < 0) return;
    int nrows = C[myp] - chunk * TILE_M;
    if (nrows > TILE_M) nrows = TILE_M;

    // ---- B loads HOISTED to registers (64 floats); the scan + perm phase
    // below overlaps their latency. ----
    float Breg[64];
    {
        const float* Mg = table + myp * D * D;
        #pragma unroll
        for (int it = 0; it < 16; it++) {
            int qn = wid + it * 8;          // 0..127
            int q = qn >> 4, nb = qn & 15;
            int e = nb * 8 + g;
            int k0 = 16 * q + 2 * tig;
            Breg[it * 4 + 0] = Mg[(k0    ) * D + e];
            Breg[it * 4 + 1] = Mg[(k0 + 1) * D + e];
            Breg[it * 4 + 2] = Mg[(k0 + 8) * D + e];
            Breg[it * 4 + 3] = Mg[(k0 + 9) * D + e];
        }
    }

    // ---- exclusive scan over per-thread counts of group myp ----
    unsigned lc = (unsigned)((cnt >> (myp * 7)) & 127);
    unsigned v = lc;
    #pragma unroll
    for (int d2 = 1; d2 < 32; d2 <<= 1) {
        unsigned n = __shfl_up_sync(0xFFFFFFFFu, v, d2);
        if (lane >= d2) v += n;
    }
    if (lane == 31) swarp[wid] = (int)v;
    __syncthreads();
    if (tid == 0) {
        int acc = 0;
        #pragma unroll
        for (int w = 0; w < 8; w++) { int t = swarp[w]; swarp[8 + w] = acc; acc += t; }
    }
    __syncthreads();
    int rank0 = swarp[8 + wid] + (int)(v - lc);

    // ---- extract perm (R14 form): ranks [chunk*128, chunk*128+nrows).
    // row(tid, j) = (j>>2)*1024 + 4*tid + (j&3). ----
    {
        int wstart = chunk * TILE_M;
        int wend   = wstart + nrows;
        if (rank0 < wend && rank0 + (int)lc > wstart) {
            int rank = rank0;
            #pragma unroll
            for (int j = 0; j < 64; j++) {
                int r = (rp[j >> 3] >> ((j & 7) * 4)) & 15;
                if (r == myp) {
                    if (rank >= wstart && rank < wend)
                        perm[rank - wstart] = (j >> 2) * 1024 + 4 * tid + (j & 3);
                    rank++;
                }
            }
        }
    }
    __syncthreads();      // perm ready

    // ---- A loads HOISTED (perm-dependent): 2 threads/row, 4 q each ----
    int rA = tid >> 1;
    int kh = tid & 1;
    int growA = (rA < nrows) ? perm[rA] : -1;
    float4 Areg[16];
    #pragma unroll
    for (int qq = 0; qq < 4; qq++) {
        if (growA >= 0) {
            const float4* src = (const float4*)(x + growA * D + (kh * 4 + qq) * 16);
            Areg[qq * 4 + 0] = src[0];
            Areg[qq * 4 + 1] = src[1];
            Areg[qq * 4 + 2] = src[2];
            Areg[qq * 4 + 3] = src[3];
        } else {
            Areg[qq * 4 + 0] = Areg[qq * 4 + 1] = Areg[qq * 4 + 2] = Areg[qq * 4 + 3] =
                make_float4(0.f, 0.f, 0.f, 0.f);
        }
    }

    // ---- B split + one STS.128 per slot (overlaps the A loads above) ----
    #pragma unroll
    for (int it = 0; it < 16; it++) {
        int qn = wid + it * 8;
        uint32_t h0, l0, h1, l1;
        split2(Breg[it * 4 + 0], Breg[it * 4 + 1], h0, l0);
        split2(Breg[it * 4 + 2], Breg[it * 4 + 3], h1, l1);
        *(uint4*)(base + OFF_B + qn * 512 + lane * 16) = make_uint4(h0, h1, l0, l1);
    }

    // ---- A split + STS ----
    {
        int aw = rA >> 4, rr = rA & 15, gg = rr & 7, up = rr >> 3;
        #pragma unroll
        for (int qq = 0; qq < 4; qq++) {
            int q = kh * 4 + qq;
            const float* kv = (const float*)&Areg[qq * 4];   // 16 consecutive floats
            #pragma unroll
            for (int t = 0; t < 4; t++) {
                uint32_t hL, lL, hH, lH;
                split2(kv[2 * t], kv[2 * t + 1], hL, lL);
                split2(kv[2 * t + 8], kv[2 * t + 9], hH, lH);
                uint32_t off = (aw * 8 + q) * 512 + (gg * 4 + t) * 16 + up * 4;
                *(uint32_t*)(base + OFF_AHI + off)     = hL;
                *(uint32_t*)(base + OFF_AHI + off + 8) = hH;
                *(uint32_t*)(base + OFF_ALO + off)     = lL;
                *(uint32_t*)(base + OFF_ALO + off + 8) = lH;
            }
        }
    }
    __syncthreads();      // A + B fragments ready

    // ---- epilogue addresses hoisted: overlap with mainloop ----
    int r0 = wid * 16 + g;
    int r1 = r0 + 8;
    int grow0 = (r0 < nrows) ? perm[r0] : -1;
    int grow1 = (r1 < nrows) ? perm[r1] : -1;
    float* op0 = out + (grow0 < 0 ? 0 : grow0) * D + 2 * tig;
    float* op1 = out + (grow1 < 0 ? 0 : grow1) * D + 2 * tig;

    // ---- mainloop: warp = 16 rows x 128 cols, K = 128, 3-way split ----
    float acc[16][4];
    #pragma unroll
    for (int nb = 0; nb < 16; nb++)
        #pragma unroll
        for (int r = 0; r < 4; r++) acc[nb][r] = 0.f;

    #pragma unroll
    for (int q = 0; q < 8; q++) {
        uint32_t abase = (wid * 8 + q) * 512 + lane * 16;
        uint4 AH = *(const uint4*)(base + OFF_AHI + abase);
        uint4 AL = *(const uint4*)(base + OFF_ALO + abase);
        #pragma unroll
        for (int nb = 0; nb < 16; nb++) {
            uint4 bv = *(const uint4*)(base + OFF_B + (q * 16 + nb) * 512 + lane * 16);
            MMA16816(acc[nb][0], acc[nb][1], acc[nb][2], acc[nb][3],
                     AH.x, AH.y, AH.z, AH.w, bv.x, bv.y);
            MMA16816(acc[nb][0], acc[nb][1], acc[nb][2], acc[nb][3],
                     AH.x, AH.y, AH.z, AH.w, bv.z, bv.w);
            MMA16816(acc[nb][0], acc[nb][1], acc[nb][2], acc[nb][3],
                     AL.x, AL.y, AL.z, AL.w, bv.x, bv.y);
        }
    }

    // ---- epilogue (addresses precomputed) ----
    #pragma unroll
    for (int nb = 0; nb < 16; nb++) {
        if (grow0 >= 0)
            *(float2*)(op0 + nb * 8) = make_float2(acc[nb][0], acc[nb][1]);
        if (grow1 >= 0)
            *(float2*)(op1 + nb * 8) = make_float2(acc[nb][2], acc[nb][3]);
    }
}

// ---------------------------------------------------------------------------
extern "C" void kernel_launch(void* const* d_in, const int* in_sizes, int n_in,
                              void* d_out, int out_size) {
    const void*  positions = d_in[0];                 // int32/int64 [T,B] auto-detected
    const float* outputs   = (const float*)d_in[1];   // f32 [T,B,128]
    const float* table     = (const float*)d_in[2];   // f32 [9,128,128]
    float*       out       = (float*)d_out;           // f32 [T,B,128]
    (void)in_sizes; (void)n_in; (void)out_size;

    static cudaError_t attr_once = cudaFuncSetAttribute(
        fused_transfer, cudaFuncAttributeMaxDynamicSharedMemorySize, SMEM_BYTES);
    (void)attr_once;

    fused_transfer<<<GRID_CTAS, NTHREADS, SMEM_BYTES>>>(positions, outputs, table, out);
}